// round 2
// baseline (speedup 1.0000x reference)
#include <cuda_runtime.h>
#include <cuda_bf16.h>
#include <math.h>
#include <stdint.h>

// Problem constants
#define B_ 4
#define N_ 2048
#define D_ 512
#define H_ 8
#define DK_ 64
#define MROWS (B_*N_)      // 8192
#define QKVC (3*D_)        // 1536
#define NEG_SLOPE 0.1f
#define SCALE 0.125f       // 1/sqrt(DK)

// Scratch (allocation-free rule: __device__ globals)
__device__ float g_q[B_*H_*N_*DK_];   // (b,h,n,dk)
__device__ float g_k[B_*H_*N_*DK_];
__device__ float g_v[B_*H_*N_*DK_];
__device__ float g_o[B_*N_*D_];       // (b,n,d) attention output, pre-projection
__device__ unsigned int g_maskbits[(size_t)B_*N_*N_/32];  // packed mask bits
__device__ int g_mask_is_bool;

// ---------------------------------------------------------------------------
// Kernel 0a: detect mask dtype via guaranteed self-edges.
// Byte interpretation of the diagonal: if the buffer is really int32,
// diag byte offsets hit int32 padding bytes for n%4!=0 -> zeros -> detected.
// ---------------------------------------------------------------------------
__global__ void detect_mask_kernel(const unsigned char* __restrict__ mask)
{
    __shared__ int ok;
    if (threadIdx.x == 0) ok = 1;
    __syncthreads();
    for (int i = threadIdx.x; i < MROWS; i += blockDim.x) {
        int b = i >> 11, n = i & 2047;
        size_t off = ((size_t)(b * N_ + n)) * N_ + n;
        if (mask[off] == 0) ok = 0;
    }
    __syncthreads();
    if (threadIdx.x == 0) g_mask_is_bool = ok;
}

// ---------------------------------------------------------------------------
// Kernel 0b: repack mask (bool-bytes OR int32) into bit array.
// One thread -> 32 mask elements -> one uint32.
// ---------------------------------------------------------------------------
__global__ __launch_bounds__(256) void repack_mask_kernel(const void* __restrict__ maskp)
{
    const int w = blockIdx.x * blockDim.x + threadIdx.x;  // word idx, B*N*N/32 total
    unsigned int bits = 0;
    if (g_mask_is_bool) {
        const unsigned int* m = (const unsigned int*)maskp;  // 4 bools per word
        #pragma unroll
        for (int j = 0; j < 8; j++) {
            unsigned int v = m[(size_t)w * 8 + j];
            bits |= ((v & 0x000000FFu) ? 1u : 0u) << (j * 4 + 0);
            bits |= ((v & 0x0000FF00u) ? 1u : 0u) << (j * 4 + 1);
            bits |= ((v & 0x00FF0000u) ? 1u : 0u) << (j * 4 + 2);
            bits |= ((v & 0xFF000000u) ? 1u : 0u) << (j * 4 + 3);
        }
    } else {
        const int4* m = (const int4*)maskp;  // int32 mask
        #pragma unroll
        for (int j = 0; j < 8; j++) {
            int4 v = m[(size_t)w * 8 + j];
            bits |= (v.x ? 1u : 0u) << (j * 4 + 0);
            bits |= (v.y ? 1u : 0u) << (j * 4 + 1);
            bits |= (v.z ? 1u : 0u) << (j * 4 + 2);
            bits |= (v.w ? 1u : 0u) << (j * 4 + 3);
        }
    }
    g_maskbits[w] = bits;
}

// ---------------------------------------------------------------------------
// Kernel 1: QKV projection.  C = x(8192x512) @ Wqkv(512x1536), scattered into
// head-major g_q/g_k/g_v.  64x64 tile, 256 threads, 4x4 micro-tile.
// ---------------------------------------------------------------------------
__global__ __launch_bounds__(256) void qkv_gemm_kernel(
    const float* __restrict__ x, const float* __restrict__ W)
{
    __shared__ float As[16][68];  // [kk][m], padded
    __shared__ float Bs[16][64];  // [kk][n]

    const int tid = threadIdx.x;
    const int tx = tid & 15, ty = tid >> 4;
    const int rowbase = blockIdx.y * 64;
    const int colbase = blockIdx.x * 64;

    float acc[4][4] = {};

    for (int k0 = 0; k0 < 512; k0 += 16) {
        #pragma unroll
        for (int i = 0; i < 4; i++) {
            int idx = tid + i * 256;
            int kk = idx & 15, m = idx >> 4;
            As[kk][m] = x[(size_t)(rowbase + m) * 512 + k0 + kk];
        }
        #pragma unroll
        for (int i = 0; i < 4; i++) {
            int idx = tid + i * 256;
            int n = idx & 63, kk = idx >> 6;
            Bs[kk][n] = W[(size_t)(k0 + kk) * QKVC + colbase + n];
        }
        __syncthreads();
        #pragma unroll
        for (int kk = 0; kk < 16; kk++) {
            float4 a4 = *(const float4*)&As[kk][ty * 4];
            float4 b4 = *(const float4*)&Bs[kk][tx * 4];
            const float* af = (const float*)&a4;
            const float* bf = (const float*)&b4;
            #pragma unroll
            for (int i = 0; i < 4; i++)
                #pragma unroll
                for (int j = 0; j < 4; j++)
                    acc[i][j] += af[i] * bf[j];
        }
        __syncthreads();
    }

    // Scatter into g_q/g_k/g_v head-major layout
    #pragma unroll
    for (int i = 0; i < 4; i++) {
        int r = rowbase + ty * 4 + i;
        int b = r >> 11;           // r / 2048
        int n = r & 2047;
        #pragma unroll
        for (int j = 0; j < 4; j++) {
            int c = colbase + tx * 4 + j;
            int which = (c >= 1024) ? 2 : (c >= 512 ? 1 : 0);
            int d = c - which * 512;
            int h = d >> 6;
            int dk = d & 63;
            size_t dst = ((size_t)(b * H_ + h) * N_ + n) * DK_ + dk;
            float v = acc[i][j];
            if (which == 0)      g_q[dst] = v;
            else if (which == 1) g_k[dst] = v;
            else                 g_v[dst] = v;
        }
    }
}

// ---------------------------------------------------------------------------
// Kernel 2: flash attention.  One CTA per (b, h, 64-query tile).
// 256 threads: thread = (row 0..63, sub 0..3); sub owns 16 cols / 16 dk.
// Online softmax with -1e30 sentinel (self-edges guarantee a live entry).
// ---------------------------------------------------------------------------
#define PAD 68  // 4-float aligned, odd-in-32-banks stride

__global__ __launch_bounds__(256) void attn_kernel()
{
    extern __shared__ float sm[];
    float (*Qs)[PAD] = (float(*)[PAD])sm;
    float (*Kt)[PAD] = (float(*)[PAD])(sm + 64 * PAD);      // [dk][m]
    float (*Vs)[PAD] = (float(*)[PAD])(sm + 2 * 64 * PAD);  // [m][dk]
    float (*Ps)[PAD] = (float(*)[PAD])(sm + 3 * 64 * PAD);  // [row][col]

    const int tid = threadIdx.x;
    const int qt = blockIdx.x, h = blockIdx.y, b = blockIdx.z;
    const int qbase = qt * 64;

    const float* qptr = g_q + ((size_t)(b * H_ + h) * N_ + qbase) * DK_;
    const float* kptr = g_k + (size_t)(b * H_ + h) * N_ * DK_;
    const float* vptr = g_v + (size_t)(b * H_ + h) * N_ * DK_;

    // Load Q tile (contiguous (n,dk) => coalesced)
    #pragma unroll
    for (int i = 0; i < 16; i++) {
        int idx = tid + i * 256;
        Qs[idx >> 6][idx & 63] = qptr[idx];
    }

    const int row = tid >> 2;
    const int sub = tid & 3;
    // packed mask: row's word base; per tile add kb/32 + (sub>>1)
    const size_t rowword = ((size_t)(b * N_ + qbase + row) * N_) >> 5;
    const int subshift = (sub & 1) * 16;
    const int subword = sub >> 1;

    float m_i = -1e30f, l_i = 0.f;
    float acc_o[16];
    #pragma unroll
    for (int d = 0; d < 16; d++) acc_o[d] = 0.f;

    __syncthreads();

    for (int kt = 0; kt < N_ / 64; kt++) {
        const int kb = kt * 64;
        // Load K (transposed) and V tiles
        #pragma unroll
        for (int i = 0; i < 16; i++) {
            int idx = tid + i * 256;
            int mm = idx >> 6, dk = idx & 63;
            float kv = kptr[(size_t)kb * 64 + idx];
            float vv = vptr[(size_t)kb * 64 + idx];
            Kt[dk][mm] = kv;
            Vs[mm][dk] = vv;
        }
        __syncthreads();

        // S = Q K^T for this thread's (row, 16 cols)
        float s[16];
        #pragma unroll
        for (int c = 0; c < 16; c++) s[c] = 0.f;
        #pragma unroll 8
        for (int dk = 0; dk < 64; dk++) {
            float qv = Qs[row][dk];
            const float4* kp = (const float4*)&Kt[dk][sub * 16];
            float4 k4[4];
            k4[0] = kp[0]; k4[1] = kp[1]; k4[2] = kp[2]; k4[3] = kp[3];
            const float* kf = (const float*)k4;
            #pragma unroll
            for (int c = 0; c < 16; c++) s[c] += qv * kf[c];
        }

        // Mask (16 bits from packed array) + scale, tile row-max
        unsigned int m16 = g_maskbits[rowword + (kb >> 5) + subword] >> subshift;
        float tm = -1e30f;
        #pragma unroll
        for (int c = 0; c < 16; c++) {
            bool keep = (m16 >> c) & 1u;
            s[c] = keep ? s[c] * SCALE : -1e30f;
            tm = fmaxf(tm, s[c]);
        }
        tm = fmaxf(tm, __shfl_xor_sync(0xffffffffu, tm, 1));
        tm = fmaxf(tm, __shfl_xor_sync(0xffffffffu, tm, 2));

        float m_new = fmaxf(m_i, tm);
        float corr = __expf(m_i - m_new);  // both -1e30 => exp(0)=1 (bogus mass wiped later)

        float rsum = 0.f;
        #pragma unroll
        for (int c = 0; c < 16; c++) {
            float p = __expf(s[c] - m_new);
            Ps[row][sub * 16 + c] = p;
            rsum += p;
        }
        rsum += __shfl_xor_sync(0xffffffffu, rsum, 1);
        rsum += __shfl_xor_sync(0xffffffffu, rsum, 2);

        l_i = l_i * corr + rsum;
        m_i = m_new;
        #pragma unroll
        for (int d = 0; d < 16; d++) acc_o[d] *= corr;

        __syncthreads();  // Ps visible across subs

        // O += P @ V  (thread: row, dk slice sub*16..+15)
        #pragma unroll 8
        for (int c = 0; c < 64; c++) {
            float p = Ps[row][c];
            const float4* vp = (const float4*)&Vs[c][sub * 16];
            float4 v4[4];
            v4[0] = vp[0]; v4[1] = vp[1]; v4[2] = vp[2]; v4[3] = vp[3];
            const float* vf = (const float*)v4;
            #pragma unroll
            for (int d = 0; d < 16; d++) acc_o[d] += p * vf[d];
        }
        __syncthreads();  // before next tile overwrites Kt/Vs (and before next Ps write)
    }

    const float inv = 1.f / l_i;
    float* optr = g_o + ((size_t)b * N_ + qbase + row) * D_ + h * DK_ + sub * 16;
    #pragma unroll
    for (int v = 0; v < 4; v++) {
        float4 o4;
        o4.x = acc_o[v * 4 + 0] * inv;
        o4.y = acc_o[v * 4 + 1] * inv;
        o4.z = acc_o[v * 4 + 2] * inv;
        o4.w = acc_o[v * 4 + 3] * inv;
        *(float4*)(optr + v * 4) = o4;
    }
}

// ---------------------------------------------------------------------------
// Kernel 3: output projection + bias + LeakyReLU.
// C = g_o(8192x512) @ Wout(512x512) + bout, leaky.
// ---------------------------------------------------------------------------
__global__ __launch_bounds__(256) void out_gemm_kernel(
    const float* __restrict__ W, const float* __restrict__ bias,
    float* __restrict__ out)
{
    __shared__ float As[16][68];
    __shared__ float Bs[16][64];

    const int tid = threadIdx.x;
    const int tx = tid & 15, ty = tid >> 4;
    const int rowbase = blockIdx.y * 64;
    const int colbase = blockIdx.x * 64;

    float acc[4][4] = {};

    for (int k0 = 0; k0 < 512; k0 += 16) {
        #pragma unroll
        for (int i = 0; i < 4; i++) {
            int idx = tid + i * 256;
            int kk = idx & 15, m = idx >> 4;
            As[kk][m] = g_o[(size_t)(rowbase + m) * 512 + k0 + kk];
        }
        #pragma unroll
        for (int i = 0; i < 4; i++) {
            int idx = tid + i * 256;
            int n = idx & 63, kk = idx >> 6;
            Bs[kk][n] = W[(size_t)(k0 + kk) * 512 + colbase + n];
        }
        __syncthreads();
        #pragma unroll
        for (int kk = 0; kk < 16; kk++) {
            float4 a4 = *(const float4*)&As[kk][ty * 4];
            float4 b4 = *(const float4*)&Bs[kk][tx * 4];
            const float* af = (const float*)&a4;
            const float* bf = (const float*)&b4;
            #pragma unroll
            for (int i = 0; i < 4; i++)
                #pragma unroll
                for (int j = 0; j < 4; j++)
                    acc[i][j] += af[i] * bf[j];
        }
        __syncthreads();
    }

    int cb = colbase + tx * 4;
    float4 bb = *(const float4*)&bias[cb];
    const float* bbf = (const float*)&bb;
    #pragma unroll
    for (int i = 0; i < 4; i++) {
        int r = rowbase + ty * 4 + i;
        float4 o4;
        float* of = (float*)&o4;
        #pragma unroll
        for (int j = 0; j < 4; j++) {
            float v = acc[i][j] + bbf[j];
            of[j] = (v >= 0.f) ? v : NEG_SLOPE * v;
        }
        *(float4*)&out[(size_t)r * 512 + cb] = o4;
    }
}

// ---------------------------------------------------------------------------
extern "C" void kernel_launch(void* const* d_in, const int* in_sizes, int n_in,
                              void* d_out, int out_size)
{
    const float* x    = (const float*)d_in[0];
    const void*  mask = d_in[1];                 // bool bytes OR int32 — detected on device
    const float* Wqkv = (const float*)d_in[2];
    const float* Wout = (const float*)d_in[3];
    const float* bout = (const float*)d_in[4];
    float* out        = (float*)d_out;

    detect_mask_kernel<<<1, 256>>>((const unsigned char*)mask);
    repack_mask_kernel<<<(B_*N_*N_/32) / 256, 256>>>(mask);

    qkv_gemm_kernel<<<dim3(QKVC / 64, MROWS / 64), 256>>>(x, Wqkv);

    const int smem_bytes = 4 * 64 * PAD * sizeof(float);  // 69632
    cudaFuncSetAttribute(attn_kernel, cudaFuncAttributeMaxDynamicSharedMemorySize, smem_bytes);
    attn_kernel<<<dim3(N_ / 64, H_, B_), 256, smem_bytes>>>();

    out_gemm_kernel<<<dim3(512 / 64, MROWS / 64), 256>>>(Wout, bout, out);
}

// round 3
// speedup vs baseline: 4.7426x; 4.7426x over previous
#include <cuda_runtime.h>
#include <cuda_bf16.h>
#include <math.h>
#include <stdint.h>

// Problem constants
#define B_ 4
#define N_ 2048
#define D_ 512
#define H_ 8
#define DK_ 64
#define MROWS (B_*N_)      // 8192
#define QKVC (3*D_)        // 1536
#define NEG_SLOPE 0.1f
#define SCALE 0.125f       // 1/sqrt(DK)

// Scratch (allocation-free rule: __device__ globals)
__device__ float g_q[B_*H_*N_*DK_];   // (b,h,n,dk)  tf32-rounded
__device__ float g_k[B_*H_*N_*DK_];   // tf32-rounded
__device__ float g_v[B_*H_*N_*DK_];   // tf32-rounded
__device__ float g_o[B_*N_*D_];       // (b,n,d) attention output (fp32)
__device__ unsigned int g_maskbits[(size_t)B_*N_*N_/32];  // packed mask bits
__device__ int g_mask_is_bool;

__device__ __forceinline__ uint32_t f2tf32(float x) {
    uint32_t r;
    asm("cvt.rna.tf32.f32 %0, %1;" : "=r"(r) : "f"(x));
    return r;
}

__device__ __forceinline__ void mma_tf32(float c[4], const uint32_t a[4],
                                         uint32_t b0, uint32_t b1) {
    asm volatile(
        "mma.sync.aligned.m16n8k8.row.col.f32.tf32.tf32.f32 "
        "{%0,%1,%2,%3}, {%4,%5,%6,%7}, {%8,%9}, {%0,%1,%2,%3};"
        : "+f"(c[0]), "+f"(c[1]), "+f"(c[2]), "+f"(c[3])
        : "r"(a[0]), "r"(a[1]), "r"(a[2]), "r"(a[3]), "r"(b0), "r"(b1));
}

// ---------------------------------------------------------------------------
// Kernel 0a: detect mask dtype via guaranteed self-edges.
// ---------------------------------------------------------------------------
__global__ void detect_mask_kernel(const unsigned char* __restrict__ mask)
{
    __shared__ int ok;
    if (threadIdx.x == 0) ok = 1;
    __syncthreads();
    for (int i = threadIdx.x; i < MROWS; i += blockDim.x) {
        int b = i >> 11, n = i & 2047;
        size_t off = ((size_t)(b * N_ + n)) * N_ + n;
        if (mask[off] == 0) ok = 0;
    }
    __syncthreads();
    if (threadIdx.x == 0) g_mask_is_bool = ok;
}

// ---------------------------------------------------------------------------
// Kernel 0b: repack mask (bool-bytes OR int32) into bit array.
// ---------------------------------------------------------------------------
__global__ __launch_bounds__(256) void repack_mask_kernel(const void* __restrict__ maskp)
{
    const int w = blockIdx.x * blockDim.x + threadIdx.x;
    unsigned int bits = 0;
    if (g_mask_is_bool) {
        const unsigned int* m = (const unsigned int*)maskp;
        #pragma unroll
        for (int j = 0; j < 8; j++) {
            unsigned int v = m[(size_t)w * 8 + j];
            bits |= ((v & 0x000000FFu) ? 1u : 0u) << (j * 4 + 0);
            bits |= ((v & 0x0000FF00u) ? 1u : 0u) << (j * 4 + 1);
            bits |= ((v & 0x00FF0000u) ? 1u : 0u) << (j * 4 + 2);
            bits |= ((v & 0xFF000000u) ? 1u : 0u) << (j * 4 + 3);
        }
    } else {
        const int4* m = (const int4*)maskp;
        #pragma unroll
        for (int j = 0; j < 8; j++) {
            int4 v = m[(size_t)w * 8 + j];
            bits |= (v.x ? 1u : 0u) << (j * 4 + 0);
            bits |= (v.y ? 1u : 0u) << (j * 4 + 1);
            bits |= (v.z ? 1u : 0u) << (j * 4 + 2);
            bits |= (v.w ? 1u : 0u) << (j * 4 + 3);
        }
    }
    g_maskbits[w] = bits;
}

// ---------------------------------------------------------------------------
// Kernel 1: QKV projection (fp32 SIMT, near FFMA floor).  Scatters head-major
// q/k/v, rounded to tf32 so the attention mma consumes bits directly.
// ---------------------------------------------------------------------------
__global__ __launch_bounds__(256) void qkv_gemm_kernel(
    const float* __restrict__ x, const float* __restrict__ W)
{
    __shared__ float As[16][68];
    __shared__ float Bs[16][64];

    const int tid = threadIdx.x;
    const int tx = tid & 15, ty = tid >> 4;
    const int rowbase = blockIdx.y * 64;
    const int colbase = blockIdx.x * 64;

    float acc[4][4] = {};

    for (int k0 = 0; k0 < 512; k0 += 16) {
        #pragma unroll
        for (int i = 0; i < 4; i++) {
            int idx = tid + i * 256;
            int kk = idx & 15, m = idx >> 4;
            As[kk][m] = x[(size_t)(rowbase + m) * 512 + k0 + kk];
        }
        #pragma unroll
        for (int i = 0; i < 4; i++) {
            int idx = tid + i * 256;
            int n = idx & 63, kk = idx >> 6;
            Bs[kk][n] = W[(size_t)(k0 + kk) * QKVC + colbase + n];
        }
        __syncthreads();
        #pragma unroll
        for (int kk = 0; kk < 16; kk++) {
            float4 a4 = *(const float4*)&As[kk][ty * 4];
            float4 b4 = *(const float4*)&Bs[kk][tx * 4];
            const float* af = (const float*)&a4;
            const float* bf = (const float*)&b4;
            #pragma unroll
            for (int i = 0; i < 4; i++)
                #pragma unroll
                for (int j = 0; j < 4; j++)
                    acc[i][j] += af[i] * bf[j];
        }
        __syncthreads();
    }

    #pragma unroll
    for (int i = 0; i < 4; i++) {
        int r = rowbase + ty * 4 + i;
        int b = r >> 11;
        int n = r & 2047;
        #pragma unroll
        for (int j = 0; j < 4; j++) {
            int c = colbase + tx * 4 + j;
            int which = (c >= 1024) ? 2 : (c >= 512 ? 1 : 0);
            int d = c - which * 512;
            int h = d >> 6;
            int dk = d & 63;
            size_t dst = ((size_t)(b * H_ + h) * N_ + n) * DK_ + dk;
            float v = __uint_as_float(f2tf32(acc[i][j]));  // tf32-rounded
            if (which == 0)      g_q[dst] = v;
            else if (which == 1) g_k[dst] = v;
            else                 g_v[dst] = v;
        }
    }
}

// ---------------------------------------------------------------------------
// Kernel 2: tensor-core flash attention (tf32 mma.sync m16n8k8).
// CTA = 128 threads = 4 warps; warp owns 16 Q rows; tile = 64 Q x 64 K.
// Q fragments live in registers for all 32 K-tiles.
// smem pads: Ks/Ps stride 68 (bank = 4g+t4 = lane, conflict-free),
//            Vs stride 72 (bank = 8(t4+nb)+g, conflict-free).
// ---------------------------------------------------------------------------
#define KPADW 68
#define VPADW 72
#define ATTN_SMEM ((64*KPADW + 64*VPADW + 64*KPADW) * 4)  // 53248 B

__global__ __launch_bounds__(128) void attn_mma_kernel()
{
    extern __shared__ uint32_t smem[];
    uint32_t (*Ks)[KPADW] = (uint32_t(*)[KPADW])smem;                    // [key][dk]
    uint32_t (*Vs)[VPADW] = (uint32_t(*)[VPADW])(smem + 64 * KPADW);     // [key][dk]
    uint32_t (*Ps)[KPADW] = (uint32_t(*)[KPADW])(smem + 64 * (KPADW + VPADW)); // P / Q staging

    const int tid  = threadIdx.x;
    const int warp = tid >> 5;
    const int lane = tid & 31;
    const int g    = lane >> 2;   // 0..7
    const int t4   = lane & 3;    // 0..3

    const int qt = blockIdx.x, h = blockIdx.y, b = blockIdx.z;
    const int qbase = qt * 64;
    const int mrow = warp * 16;

    const float* qptr = g_q + ((size_t)(b * H_ + h) * N_ + qbase) * DK_;
    const float* kptr = g_k + (size_t)(b * H_ + h) * N_ * DK_;
    const float* vptr = g_v + (size_t)(b * H_ + h) * N_ * DK_;

    // Stage Q through smem, pull fragments into registers.
    #pragma unroll
    for (int i = 0; i < 8; i++) {
        int idx4 = tid + i * 128;            // 1024 float4 total
        int r = idx4 >> 4, c = (idx4 & 15) * 4;
        float4 qv = *(const float4*)(qptr + (size_t)r * 64 + c);
        *(uint4*)&Ps[r][c] = make_uint4(__float_as_uint(qv.x), __float_as_uint(qv.y),
                                        __float_as_uint(qv.z), __float_as_uint(qv.w));
    }
    __syncthreads();
    uint32_t qa[8][4];
    #pragma unroll
    for (int ks = 0; ks < 8; ks++) {
        qa[ks][0] = Ps[mrow + g][ks * 8 + t4];
        qa[ks][1] = Ps[mrow + g + 8][ks * 8 + t4];
        qa[ks][2] = Ps[mrow + g][ks * 8 + t4 + 4];
        qa[ks][3] = Ps[mrow + g + 8][ks * 8 + t4 + 4];
    }
    __syncthreads();

    // Per-thread softmax state for rows r0 = g, r1 = g+8 (within warp's 16 rows)
    float m0 = -1e30f, m1 = -1e30f, l0 = 0.f, l1 = 0.f;
    float o[8][4] = {};

    const int grow0 = qbase + mrow + g;          // global query row (r0)
    const size_t mword0 = (size_t)(b * N_ + grow0) * (N_ / 64);      // uint64 index
    const unsigned long long* mask64 = (const unsigned long long*)g_maskbits;

    for (int kt = 0; kt < N_ / 64; kt++) {
        const size_t kb64 = (size_t)kt * 64 * 64;  // element offset of tile
        // Load K/V tile into smem (bits already tf32-rounded)
        #pragma unroll
        for (int i = 0; i < 8; i++) {
            int idx4 = tid + i * 128;
            int r = idx4 >> 4, c = (idx4 & 15) * 4;
            float4 kv = *(const float4*)(kptr + kb64 + (size_t)r * 64 + c);
            float4 vv = *(const float4*)(vptr + kb64 + (size_t)r * 64 + c);
            *(uint4*)&Ks[r][c] = make_uint4(__float_as_uint(kv.x), __float_as_uint(kv.y),
                                            __float_as_uint(kv.z), __float_as_uint(kv.w));
            *(uint4*)&Vs[r][c] = make_uint4(__float_as_uint(vv.x), __float_as_uint(vv.y),
                                            __float_as_uint(vv.z), __float_as_uint(vv.w));
        }
        __syncthreads();

        // S = Q @ K^T (16x64 per warp)
        float s[8][4] = {};
        #pragma unroll
        for (int ks = 0; ks < 8; ks++) {
            #pragma unroll
            for (int nb = 0; nb < 8; nb++) {
                uint32_t b0 = Ks[nb * 8 + g][ks * 8 + t4];
                uint32_t b1 = Ks[nb * 8 + g][ks * 8 + t4 + 4];
                mma_tf32(s[nb], qa[ks], b0, b1);
            }
        }

        // Mask + online softmax
        unsigned long long mw0 = mask64[mword0 + kt];
        unsigned long long mw1 = mask64[mword0 + 8 * (N_ / 64) + kt];
        float tm0 = -1e30f, tm1 = -1e30f;
        #pragma unroll
        for (int nb = 0; nb < 8; nb++) {
            int sh = nb * 8 + t4 * 2;
            unsigned int b0m = (unsigned int)(mw0 >> sh) & 3u;
            unsigned int b1m = (unsigned int)(mw1 >> sh) & 3u;
            s[nb][0] = (b0m & 1u) ? s[nb][0] * SCALE : -1e30f;
            s[nb][1] = (b0m & 2u) ? s[nb][1] * SCALE : -1e30f;
            s[nb][2] = (b1m & 1u) ? s[nb][2] * SCALE : -1e30f;
            s[nb][3] = (b1m & 2u) ? s[nb][3] * SCALE : -1e30f;
            tm0 = fmaxf(tm0, fmaxf(s[nb][0], s[nb][1]));
            tm1 = fmaxf(tm1, fmaxf(s[nb][2], s[nb][3]));
        }
        tm0 = fmaxf(tm0, __shfl_xor_sync(0xffffffffu, tm0, 1));
        tm0 = fmaxf(tm0, __shfl_xor_sync(0xffffffffu, tm0, 2));
        tm1 = fmaxf(tm1, __shfl_xor_sync(0xffffffffu, tm1, 1));
        tm1 = fmaxf(tm1, __shfl_xor_sync(0xffffffffu, tm1, 2));

        float mn0 = fmaxf(m0, tm0);
        float mn1 = fmaxf(m1, tm1);
        float corr0 = __expf(m0 - mn0);
        float corr1 = __expf(m1 - mn1);
        m0 = mn0; m1 = mn1;

        float rs0 = 0.f, rs1 = 0.f;
        #pragma unroll
        for (int nb = 0; nb < 8; nb++) {
            uint32_t p00 = f2tf32(__expf(s[nb][0] - mn0));
            uint32_t p01 = f2tf32(__expf(s[nb][1] - mn0));
            uint32_t p10 = f2tf32(__expf(s[nb][2] - mn1));
            uint32_t p11 = f2tf32(__expf(s[nb][3] - mn1));
            rs0 += __uint_as_float(p00) + __uint_as_float(p01);
            rs1 += __uint_as_float(p10) + __uint_as_float(p11);
            *(uint2*)&Ps[mrow + g][nb * 8 + t4 * 2]     = make_uint2(p00, p01);
            *(uint2*)&Ps[mrow + g + 8][nb * 8 + t4 * 2] = make_uint2(p10, p11);
        }
        rs0 += __shfl_xor_sync(0xffffffffu, rs0, 1);
        rs0 += __shfl_xor_sync(0xffffffffu, rs0, 2);
        rs1 += __shfl_xor_sync(0xffffffffu, rs1, 1);
        rs1 += __shfl_xor_sync(0xffffffffu, rs1, 2);
        l0 = l0 * corr0 + rs0;
        l1 = l1 * corr1 + rs1;
        #pragma unroll
        for (int nb = 0; nb < 8; nb++) {
            o[nb][0] *= corr0; o[nb][1] *= corr0;
            o[nb][2] *= corr1; o[nb][3] *= corr1;
        }
        __syncwarp();  // Ps rows are warp-private: cross-lane visibility only

        // O += P @ V  (16x64 per warp)
        #pragma unroll
        for (int ks = 0; ks < 8; ks++) {
            uint32_t pa[4];
            pa[0] = Ps[mrow + g][ks * 8 + t4];
            pa[1] = Ps[mrow + g + 8][ks * 8 + t4];
            pa[2] = Ps[mrow + g][ks * 8 + t4 + 4];
            pa[3] = Ps[mrow + g + 8][ks * 8 + t4 + 4];
            #pragma unroll
            for (int nb = 0; nb < 8; nb++) {
                uint32_t b0 = Vs[ks * 8 + t4][nb * 8 + g];
                uint32_t b1 = Vs[ks * 8 + t4 + 4][nb * 8 + g];
                mma_tf32(o[nb], pa, b0, b1);
            }
        }
        __syncthreads();  // all warps done with Ks/Vs before next tile load
    }

    const float inv0 = 1.f / l0;
    const float inv1 = 1.f / l1;
    float* obase = g_o + ((size_t)(b * N_) + qbase + mrow) * D_ + h * DK_;
    #pragma unroll
    for (int nb = 0; nb < 8; nb++) {
        int col = nb * 8 + t4 * 2;
        float2 w0 = make_float2(o[nb][0] * inv0, o[nb][1] * inv0);
        float2 w1 = make_float2(o[nb][2] * inv1, o[nb][3] * inv1);
        *(float2*)&obase[(size_t)g * D_ + col]       = w0;
        *(float2*)&obase[(size_t)(g + 8) * D_ + col] = w1;
    }
}

// ---------------------------------------------------------------------------
// Kernel 3: output projection + bias + LeakyReLU (fp32 SIMT).
// ---------------------------------------------------------------------------
__global__ __launch_bounds__(256) void out_gemm_kernel(
    const float* __restrict__ W, const float* __restrict__ bias,
    float* __restrict__ out)
{
    __shared__ float As[16][68];
    __shared__ float Bs[16][64];

    const int tid = threadIdx.x;
    const int tx = tid & 15, ty = tid >> 4;
    const int rowbase = blockIdx.y * 64;
    const int colbase = blockIdx.x * 64;

    float acc[4][4] = {};

    for (int k0 = 0; k0 < 512; k0 += 16) {
        #pragma unroll
        for (int i = 0; i < 4; i++) {
            int idx = tid + i * 256;
            int kk = idx & 15, m = idx >> 4;
            As[kk][m] = g_o[(size_t)(rowbase + m) * 512 + k0 + kk];
        }
        #pragma unroll
        for (int i = 0; i < 4; i++) {
            int idx = tid + i * 256;
            int n = idx & 63, kk = idx >> 6;
            Bs[kk][n] = W[(size_t)(k0 + kk) * 512 + colbase + n];
        }
        __syncthreads();
        #pragma unroll
        for (int kk = 0; kk < 16; kk++) {
            float4 a4 = *(const float4*)&As[kk][ty * 4];
            float4 b4 = *(const float4*)&Bs[kk][tx * 4];
            const float* af = (const float*)&a4;
            const float* bf = (const float*)&b4;
            #pragma unroll
            for (int i = 0; i < 4; i++)
                #pragma unroll
                for (int j = 0; j < 4; j++)
                    acc[i][j] += af[i] * bf[j];
        }
        __syncthreads();
    }

    int cb = colbase + tx * 4;
    float4 bb = *(const float4*)&bias[cb];
    const float* bbf = (const float*)&bb;
    #pragma unroll
    for (int i = 0; i < 4; i++) {
        int r = rowbase + ty * 4 + i;
        float4 o4;
        float* of = (float*)&o4;
        #pragma unroll
        for (int j = 0; j < 4; j++) {
            float v = acc[i][j] + bbf[j];
            of[j] = (v >= 0.f) ? v : NEG_SLOPE * v;
        }
        *(float4*)&out[(size_t)r * 512 + cb] = o4;
    }
}

// ---------------------------------------------------------------------------
extern "C" void kernel_launch(void* const* d_in, const int* in_sizes, int n_in,
                              void* d_out, int out_size)
{
    const float* x    = (const float*)d_in[0];
    const void*  mask = d_in[1];
    const float* Wqkv = (const float*)d_in[2];
    const float* Wout = (const float*)d_in[3];
    const float* bout = (const float*)d_in[4];
    float* out        = (float*)d_out;

    detect_mask_kernel<<<1, 256>>>((const unsigned char*)mask);
    repack_mask_kernel<<<(B_*N_*N_/32) / 256, 256>>>(mask);

    qkv_gemm_kernel<<<dim3(QKVC / 64, MROWS / 64), 256>>>(x, Wqkv);

    cudaFuncSetAttribute(attn_mma_kernel, cudaFuncAttributeMaxDynamicSharedMemorySize, ATTN_SMEM);
    attn_mma_kernel<<<dim3(N_ / 64, H_, B_), 128, ATTN_SMEM>>>();

    out_gemm_kernel<<<dim3(512 / 64, MROWS / 64), 256>>>(Wout, bout, out);
}